// round 1
// baseline (speedup 1.0000x reference)
#include <cuda_runtime.h>
#include <cstdint>
#include <cstddef>

// ============================================================================
// RNNSequence: h_t = tanh(x_t @ W_ih + h_{t-1} @ W_hh + b), out[b,t,:] = h_t
// B=32, T=2048, D_IN=512, D_H=512, fp32.
//
// Phase 1: gemm_xw writes xw = x@W_ih + b into d_out (65536x512 GEMM).
// Phase 2: rnn_scan: 16 clusters x 8 CTAs. Cluster c owns batches {2c, 2c+1}.
//          CTA rank r owns output columns [64r, 64r+64). W_hh slice lives in
//          smem for all 2048 steps; h is exchanged via DSMEM + cluster barrier.
// ============================================================================

constexpr int SEQ = 2048;
constexpr int DH  = 512;

// ---------------------------------------------------------------------------
// Phase 1: C[M,512] = A[M,512] @ B[512,512] + bias, classic 128x128x16 SGEMM
// ---------------------------------------------------------------------------
__global__ __launch_bounds__(256, 2) void gemm_xw(const float* __restrict__ A,
                                                  const float* __restrict__ B,
                                                  const float* __restrict__ bias,
                                                  float* __restrict__ C) {
    constexpr int K = 512, N = 512;
    __shared__ float As[16][128];
    __shared__ float Bs[16][128];

    const int tid  = threadIdx.x;
    const int row0 = blockIdx.y * 128;
    const int col0 = blockIdx.x * 128;
    const int ty   = tid >> 4;   // 0..15
    const int tx   = tid & 15;   // 0..15

    float acc[8][8];
#pragma unroll
    for (int i = 0; i < 8; i++)
#pragma unroll
        for (int j = 0; j < 8; j++) acc[i][j] = 0.0f;

    for (int k0 = 0; k0 < K; k0 += 16) {
        // Load A tile 128x16 (transposed into As[k][m])
#pragma unroll
        for (int i = 0; i < 2; i++) {
            int s  = tid + i * 256;          // 0..511
            int m  = s & 127;
            int kg = (s >> 7) << 2;          // 0,4,8,12
            float4 v = *(const float4*)(A + (size_t)(row0 + m) * K + (k0 + kg));
            As[kg + 0][m] = v.x;
            As[kg + 1][m] = v.y;
            As[kg + 2][m] = v.z;
            As[kg + 3][m] = v.w;
        }
        // Load B tile 16x128
#pragma unroll
        for (int i = 0; i < 2; i++) {
            int s  = tid + i * 256;
            int n4 = (s & 31) << 2;          // 0..124
            int kk = s >> 5;                 // 0..15
            *(float4*)(&Bs[kk][n4]) =
                *(const float4*)(B + (size_t)(k0 + kk) * N + col0 + n4);
        }
        __syncthreads();

#pragma unroll
        for (int kk = 0; kk < 16; kk++) {
            float a[8], b[8];
            *(float4*)(a)     = *(const float4*)(&As[kk][ty * 8]);
            *(float4*)(a + 4) = *(const float4*)(&As[kk][ty * 8 + 4]);
            *(float4*)(b)     = *(const float4*)(&Bs[kk][tx * 8]);
            *(float4*)(b + 4) = *(const float4*)(&Bs[kk][tx * 8 + 4]);
#pragma unroll
            for (int i = 0; i < 8; i++)
#pragma unroll
                for (int j = 0; j < 8; j++)
                    acc[i][j] += a[i] * b[j];
        }
        __syncthreads();
    }

    float bv[8];
    *(float4*)(bv)     = *(const float4*)(bias + col0 + tx * 8);
    *(float4*)(bv + 4) = *(const float4*)(bias + col0 + tx * 8 + 4);

#pragma unroll
    for (int i = 0; i < 8; i++) {
        float4 o0, o1;
        o0.x = acc[i][0] + bv[0];
        o0.y = acc[i][1] + bv[1];
        o0.z = acc[i][2] + bv[2];
        o0.w = acc[i][3] + bv[3];
        o1.x = acc[i][4] + bv[4];
        o1.y = acc[i][5] + bv[5];
        o1.z = acc[i][6] + bv[6];
        o1.w = acc[i][7] + bv[7];
        float* cp = C + (size_t)(row0 + ty * 8 + i) * N + col0 + tx * 8;
        *(float4*)(cp)     = o0;
        *(float4*)(cp + 4) = o1;
    }
}

// ---------------------------------------------------------------------------
// Phase 2: clustered sequential scan
// ---------------------------------------------------------------------------
constexpr int WT_ROWPAD = 516;                       // 512 + 4 (bank-phase pad)
constexpr int WT_FLOATS = 64 * WT_ROWPAD;
constexpr size_t SMEM_SCAN =
    (size_t)WT_FLOATS * 4 +      // W_hh^T slice [64][516] fp32     = 132096 B
    2 * 512 * 8 +                // h double buffer, float2 per k   =   8192 B
    4 * 64 * 8;                  // cross-kq reduction scratch      =   2048 B

__device__ __forceinline__ uint32_t smem_u32(const void* p) {
    return (uint32_t)__cvta_generic_to_shared(p);
}

// Precise tanh robust to --use_fast_math (expm1f is never substituted).
__device__ __forceinline__ float tanh_precise(float x) {
    float ax = fabsf(x);
    float em = expm1f(-2.0f * ax);          // in (-1, 0]
    float r  = -em / (2.0f + em);           // = tanh(|x|)
    return copysignf(r, x);
}

__global__ __launch_bounds__(256, 1) void rnn_scan(float* __restrict__ out,
                                                   const float* __restrict__ Whh) {
    extern __shared__ char smem[];
    float*  Wt   = (float*)smem;                                  // [64][516]
    float2* hbuf = (float2*)(smem + (size_t)WT_FLOATS * 4);       // [2][512]
    float2* red  = (float2*)(smem + (size_t)WT_FLOATS * 4 + 2 * 512 * 8); // [4][64]

    const int tid   = threadIdx.x;
    const int r     = blockIdx.x & 7;    // rank in cluster
    const int c     = blockIdx.x >> 3;   // cluster id (0..15)
    const int jbase = r * 64;

    // Load W_hh[:, jbase : jbase+64] transposed: Wt[j][k] = Whh[k][jbase+j]
    for (int idx = tid; idx < 512 * 64; idx += 256) {
        int k = idx >> 6;
        int j = idx & 63;
        Wt[j * WT_ROWPAD + k] = Whh[(size_t)k * 512 + jbase + j];
    }
    // h0 = 0 (both buffers)
    for (int idx = tid; idx < 1024; idx += 256)
        hbuf[idx] = make_float2(0.0f, 0.0f);
    __syncthreads();
    // All cluster CTAs ready before anyone scatters into our hbuf
    asm volatile("barrier.cluster.arrive.aligned;" ::: "memory");
    asm volatile("barrier.cluster.wait.aligned;" ::: "memory");

    // k-loop work split: thread = (j, kq), j in [0,64), kq in [0,4)
    const int j  = tid & 63;
    const int kq = tid >> 6;
    const float* wrow = Wt + j * WT_ROWPAD + kq * 128;

    // reduction/output role (tid < 128): (rb, rj)
    const int rb    = (tid >> 6) & 1;
    const int rj    = tid & 63;
    const int batch = c * 2 + rb;
    const int gj    = jbase + rj;
    float* outp = out + (size_t)batch * SEQ * DH + gj;

    // DSMEM peer addresses of hbuf in every cluster CTA
    uint32_t hb = smem_u32(hbuf);
    uint32_t peer[8];
#pragma unroll
    for (int p = 0; p < 8; p++)
        asm("mapa.shared::cluster.u32 %0, %1, %2;"
            : "=r"(peer[p]) : "r"(hb), "r"(p));

    for (int t = 0; t < SEQ; ++t) {
        const int cur = t & 1;

        // Prefetch xw[b,t,gj] early; latency hidden under the k-loop.
        float xwv = 0.0f;
        if (tid < 128) xwv = outp[(size_t)t * DH];

        const float2* hc = hbuf + cur * 512 + kq * 128;
        float aA0 = 0.f, aA1 = 0.f, aB0 = 0.f, aB1 = 0.f;
#pragma unroll 8
        for (int kk = 0; kk < 128; kk += 4) {
            float4 wv  = *(const float4*)(wrow + kk);
            float4 h01 = *(const float4*)(hc + kk);      // (h0[k],h1[k],h0[k+1],h1[k+1])
            float4 h23 = *(const float4*)(hc + kk + 2);
            aA0 += h01.x * wv.x;  aB0 += h01.y * wv.x;
            aA1 += h01.z * wv.y;  aB1 += h01.w * wv.y;
            aA0 += h23.x * wv.z;  aB0 += h23.y * wv.z;
            aA1 += h23.z * wv.w;  aB1 += h23.w * wv.w;
        }
        red[kq * 64 + j] = make_float2(aA0 + aA1, aB0 + aB1);
        __syncthreads();

        if (tid < 128) {
            float2 p0 = red[rj];
            float2 p1 = red[64 + rj];
            float2 p2 = red[128 + rj];
            float2 p3 = red[192 + rj];
            float s = rb ? ((p0.y + p1.y) + (p2.y + p3.y))
                         : ((p0.x + p1.x) + (p2.x + p3.x));
            s += xwv;
            float hn = tanh_precise(s);
            outp[(size_t)t * DH] = hn;

            // Scatter h_new into next-step buffer of every cluster CTA.
            uint32_t off = (uint32_t)(((cur ^ 1) * 512 + gj) * 8 + rb * 4);
#pragma unroll
            for (int p = 0; p < 8; p++)
                asm volatile("st.shared::cluster.f32 [%0], %1;"
                             :: "r"(peer[p] + off), "f"(hn) : "memory");
        }
        // Release our writes, acquire peers' writes.
        asm volatile("barrier.cluster.arrive.aligned;" ::: "memory");
        asm volatile("barrier.cluster.wait.aligned;" ::: "memory");
    }
}

// ---------------------------------------------------------------------------
// Launch
// ---------------------------------------------------------------------------
extern "C" void kernel_launch(void* const* d_in, const int* in_sizes, int n_in,
                              void* d_out, int out_size) {
    const float* x    = (const float*)d_in[0];  // [32,2048,512]
    const float* W_ih = (const float*)d_in[1];  // [512,512]
    const float* W_hh = (const float*)d_in[2];  // [512,512]
    const float* bias = (const float*)d_in[3];  // [512]
    float* out = (float*)d_out;                 // [32,2048,512]

    // Phase 1: xw into d_out. M = 32*2048 = 65536 rows.
    dim3 ggrid(512 / 128, (32 * SEQ) / 128);    // (4, 512)
    gemm_xw<<<ggrid, 256>>>(x, W_ih, bias, out);

    // Phase 2: clustered scan, 16 clusters x 8 CTAs, 142336 B dynamic smem.
    cudaFuncSetAttribute(rnn_scan, cudaFuncAttributeMaxDynamicSharedMemorySize,
                         (int)SMEM_SCAN);

    cudaLaunchConfig_t cfg = {};
    cfg.gridDim          = dim3(128, 1, 1);
    cfg.blockDim         = dim3(256, 1, 1);
    cfg.dynamicSmemBytes = SMEM_SCAN;
    cfg.stream           = 0;

    cudaLaunchAttribute attrs[1];
    attrs[0].id = cudaLaunchAttributeClusterDimension;
    attrs[0].val.clusterDim.x = 8;
    attrs[0].val.clusterDim.y = 1;
    attrs[0].val.clusterDim.z = 1;
    cfg.attrs    = attrs;
    cfg.numAttrs = 1;

    cudaLaunchKernelEx(&cfg, rnn_scan, out, W_hh);
}

// round 2
// speedup vs baseline: 1.1594x; 1.1594x over previous
#include <cuda_runtime.h>
#include <cstdint>
#include <cstddef>

// ============================================================================
// RNNSequence: h_t = tanh(x_t @ W_ih + h_{t-1} @ W_hh + b), out[b,t,:] = h_t
// B=32, T=2048, D_IN=512, D_H=512, fp32.
//
// Phase 1: gemm_xw writes xw = x@W_ih + b into d_out (65536x512, f32x2 FMA).
// Phase 2: rnn_scan: 16 clusters x 8 CTAs, batches {2c,2c+1} per cluster.
//          W_hh slice lives in REGISTERS (64 f32x2 pairs/thread); h exchanged
//          via DSMEM broadcast + cluster barrier; reduction via shuffles.
// ============================================================================

constexpr int SEQ = 2048;
constexpr int DH  = 512;

__device__ __forceinline__ unsigned long long pack2(float lo, float hi) {
    unsigned long long r;
    unsigned l = __float_as_uint(lo), h = __float_as_uint(hi);
    asm("mov.b64 %0, {%1, %2};" : "=l"(r) : "r"(l), "r"(h));
    return r;
}
__device__ __forceinline__ void unpack2(unsigned long long v, float& lo, float& hi) {
    unsigned l, h;
    asm("mov.b64 {%0, %1}, %2;" : "=r"(l), "=r"(h) : "l"(v));
    lo = __uint_as_float(l);
    hi = __uint_as_float(h);
}
__device__ __forceinline__ void fma2(unsigned long long& acc,
                                     unsigned long long a, unsigned long long b) {
    asm("fma.rn.f32x2 %0, %1, %2, %0;" : "+l"(acc) : "l"(a), "l"(b));
}

// ---------------------------------------------------------------------------
// Phase 1: C[M,512] = A[M,512] @ B[512,512] + bias  (128x128x16, f32x2)
// ---------------------------------------------------------------------------
__global__ __launch_bounds__(256, 2) void gemm_xw(const float* __restrict__ A,
                                                  const float* __restrict__ B,
                                                  const float* __restrict__ bias,
                                                  float* __restrict__ C) {
    constexpr int K = 512, N = 512;
    __shared__ __align__(16) float As[16][128];
    __shared__ __align__(16) float Bs[16][128];

    const int tid  = threadIdx.x;
    const int row0 = blockIdx.y * 128;
    const int col0 = blockIdx.x * 128;
    const int ty   = tid >> 4;   // 0..15
    const int tx   = tid & 15;   // 0..15

    unsigned long long acc2[8][4];
#pragma unroll
    for (int i = 0; i < 8; i++)
#pragma unroll
        for (int j = 0; j < 4; j++) acc2[i][j] = 0ULL;

    for (int k0 = 0; k0 < K; k0 += 16) {
#pragma unroll
        for (int i = 0; i < 2; i++) {
            int s  = tid + i * 256;          // 0..511
            int m  = s & 127;
            int kg = (s >> 7) << 2;          // 0,4,8,12
            float4 v = *(const float4*)(A + (size_t)(row0 + m) * K + (k0 + kg));
            As[kg + 0][m] = v.x;
            As[kg + 1][m] = v.y;
            As[kg + 2][m] = v.z;
            As[kg + 3][m] = v.w;
        }
#pragma unroll
        for (int i = 0; i < 2; i++) {
            int s  = tid + i * 256;
            int n4 = (s & 31) << 2;
            int kk = s >> 5;
            *(float4*)(&Bs[kk][n4]) =
                *(const float4*)(B + (size_t)(k0 + kk) * N + col0 + n4);
        }
        __syncthreads();

#pragma unroll
        for (int kk = 0; kk < 16; kk++) {
            float a[8];
            *(float4*)(a)     = *(const float4*)(&As[kk][ty * 8]);
            *(float4*)(a + 4) = *(const float4*)(&As[kk][ty * 8 + 4]);
            ulonglong2 b01 = *(const ulonglong2*)(&Bs[kk][tx * 8]);
            ulonglong2 b23 = *(const ulonglong2*)(&Bs[kk][tx * 8 + 4]);
            unsigned long long bb[4] = {b01.x, b01.y, b23.x, b23.y};
#pragma unroll
            for (int i = 0; i < 8; i++) {
                unsigned au = __float_as_uint(a[i]);
                unsigned long long ad;
                asm("mov.b64 %0, {%1, %1};" : "=l"(ad) : "r"(au));
#pragma unroll
                for (int j2 = 0; j2 < 4; j2++) fma2(acc2[i][j2], ad, bb[j2]);
            }
        }
        __syncthreads();
    }

    float bv[8];
    *(float4*)(bv)     = *(const float4*)(bias + col0 + tx * 8);
    *(float4*)(bv + 4) = *(const float4*)(bias + col0 + tx * 8 + 4);

#pragma unroll
    for (int i = 0; i < 8; i++) {
        float o[8];
#pragma unroll
        for (int j2 = 0; j2 < 4; j2++) {
            float lo, hi;
            unpack2(acc2[i][j2], lo, hi);
            o[j2 * 2]     = lo + bv[j2 * 2];
            o[j2 * 2 + 1] = hi + bv[j2 * 2 + 1];
        }
        float* cp = C + (size_t)(row0 + ty * 8 + i) * N + col0 + tx * 8;
        *(float4*)(cp)     = *(float4*)(o);
        *(float4*)(cp + 4) = *(float4*)(o + 4);
    }
}

// ---------------------------------------------------------------------------
// Phase 2: clustered sequential scan, W in registers
// ---------------------------------------------------------------------------
// h layout: hbuf[buf(2)][batch(2)][4*136]  (chunk stride 136 floats avoids
// bank conflicts between the 4 kq broadcast groups; 136*4B is 16B-aligned)
constexpr int HCH   = 136;               // padded per-kq chunk stride (floats)
constexpr int HBAT  = 4 * HCH;           // 544 floats per (buf,batch)

__device__ __forceinline__ uint32_t smem_u32(const void* p) {
    return (uint32_t)__cvta_generic_to_shared(p);
}

// Precise tanh robust to --use_fast_math (expm1f is never substituted).
__device__ __forceinline__ float tanh_precise(float x) {
    float ax = fabsf(x);
    float em = expm1f(-2.0f * ax);          // in (-1, 0]
    float r  = -em / (2.0f + em);           // = tanh(|x|)
    return copysignf(r, x);
}

__global__ __launch_bounds__(256, 1) void rnn_scan(float* __restrict__ out,
                                                   const float* __restrict__ Whh) {
    __shared__ __align__(16) float hbuf[2][2][HBAT];

    const int tid   = threadIdx.x;
    const int r     = blockIdx.x & 7;    // rank in cluster
    const int c     = blockIdx.x >> 3;   // cluster id (0..15)
    const int jbase = r * 64;

    const int j  = tid >> 2;             // 0..63  column within slice
    const int kq = tid & 3;              // 0..3   k-quarter (128 k each)
    const int col = jbase + j;
    const int k0  = kq * 128;

    // W_hh slice into registers: w2[i] = (Whh[k0+2i][col], Whh[k0+2i+1][col])
    unsigned long long w2[64];
#pragma unroll
    for (int i = 0; i < 64; i++) {
        float lo = Whh[(size_t)(k0 + 2 * i)     * 512 + col];
        float hi = Whh[(size_t)(k0 + 2 * i + 1) * 512 + col];
        w2[i] = pack2(lo, hi);
    }

    // zero both h buffers
    for (int idx = tid; idx < 2 * 2 * HBAT; idx += 256)
        ((float*)hbuf)[idx] = 0.0f;
    __syncthreads();
    asm volatile("barrier.cluster.arrive.aligned;" ::: "memory");
    asm volatile("barrier.cluster.wait.aligned;" ::: "memory");

    // writer role: kq==0 -> batch 0 of this cluster, kq==1 -> batch 1
    const int batch = kq;                        // valid when kq < 2
    const int gj    = jbase + j;
    float* outp = out + ((size_t)(c * 2 + (kq < 2 ? batch : 0)) * SEQ) * DH + gj;
    const uint32_t hoff =                         // scatter byte offset pieces
        (uint32_t)((batch < 2 ? batch : 0) * HBAT + (gj >> 7) * HCH + (gj & 127)) * 4;

    // DSMEM peer addresses of hbuf
    uint32_t hb = smem_u32(hbuf);
    uint32_t peer[8];
#pragma unroll
    for (int p = 0; p < 8; p++)
        asm("mapa.shared::cluster.u32 %0, %1, %2;"
            : "=r"(peer[p]) : "r"(hb), "r"(p));

    for (int t = 0; t < SEQ; ++t) {
        const int cur = t & 1;

        // prefetch xw[b,t,gj] (writers only); latency hidden under compute
        float xwv = 0.0f;
        if (kq < 2) xwv = outp[(size_t)t * DH];

        const ulonglong2* hA =
            (const ulonglong2*)&hbuf[cur][0][kq * HCH];
        const ulonglong2* hB =
            (const ulonglong2*)&hbuf[cur][1][kq * HCH];

        unsigned long long aA = 0ULL, aB = 0ULL;
#pragma unroll
        for (int i = 0; i < 32; i++) {
            ulonglong2 ha = hA[i];   // (h[k],h[k+1]),(h[k+2],h[k+3]) batch 0
            ulonglong2 hb2 = hB[i];  // same, batch 1
            fma2(aA, w2[2 * i],     ha.x);
            fma2(aA, w2[2 * i + 1], ha.y);
            fma2(aB, w2[2 * i],     hb2.x);
            fma2(aB, w2[2 * i + 1], hb2.y);
        }
        float lA, hA_, lB, hB_;
        unpack2(aA, lA, hA_);
        unpack2(aB, lB, hB_);
        float pA = lA + hA_;
        float pB = lB + hB_;
        // butterfly over the 4 kq lanes of this j-group (adjacent lanes)
        pA += __shfl_xor_sync(0xffffffffu, pA, 1);
        pA += __shfl_xor_sync(0xffffffffu, pA, 2);
        pB += __shfl_xor_sync(0xffffffffu, pB, 1);
        pB += __shfl_xor_sync(0xffffffffu, pB, 2);

        if (kq < 2) {
            float s  = (kq == 0 ? pA : pB) + xwv;
            float hn = tanh_precise(s);
            outp[(size_t)t * DH] = hn;
            // scatter into next buffer of every cluster CTA
            uint32_t off = (uint32_t)((cur ^ 1) * 2 * HBAT * 4) + hoff;
#pragma unroll
            for (int p = 0; p < 8; p++)
                asm volatile("st.shared::cluster.f32 [%0], %1;"
                             :: "r"(peer[p] + off), "f"(hn) : "memory");
        }
        asm volatile("barrier.cluster.arrive.aligned;" ::: "memory");
        asm volatile("barrier.cluster.wait.aligned;" ::: "memory");
    }
}

// ---------------------------------------------------------------------------
// Launch
// ---------------------------------------------------------------------------
extern "C" void kernel_launch(void* const* d_in, const int* in_sizes, int n_in,
                              void* d_out, int out_size) {
    const float* x    = (const float*)d_in[0];  // [32,2048,512]
    const float* W_ih = (const float*)d_in[1];  // [512,512]
    const float* W_hh = (const float*)d_in[2];  // [512,512]
    const float* bias = (const float*)d_in[3];  // [512]
    float* out = (float*)d_out;                 // [32,2048,512]

    // Phase 1: xw into d_out. M = 32*2048 = 65536 rows.
    dim3 ggrid(512 / 128, (32 * SEQ) / 128);    // (4, 512)
    gemm_xw<<<ggrid, 256>>>(x, W_ih, bias, out);

    // Phase 2: clustered scan, 16 clusters x 8 CTAs.
    cudaLaunchConfig_t cfg = {};
    cfg.gridDim          = dim3(128, 1, 1);
    cfg.blockDim         = dim3(256, 1, 1);
    cfg.dynamicSmemBytes = 0;
    cfg.stream           = 0;

    cudaLaunchAttribute attrs[1];
    attrs[0].id = cudaLaunchAttributeClusterDimension;
    attrs[0].val.clusterDim.x = 8;
    attrs[0].val.clusterDim.y = 1;
    attrs[0].val.clusterDim.z = 1;
    cfg.attrs    = attrs;
    cfg.numAttrs = 1;

    cudaLaunchKernelEx(&cfg, rnn_scan, out, W_hh);
}